// round 2
// baseline (speedup 1.0000x reference)
#include <cuda_runtime.h>
#include <math.h>

#define THREADS 128
#define CHUNK   64          // codes per smem tile
#define C_DIM   64          // embedding dim
#define N_E     2048        // codebook size
#define HW      4096        // H*W

__device__ int   g_hist[N_E];
__device__ float g_partial[1024];

__global__ void vq_zero() {
    int t = blockIdx.x * blockDim.x + threadIdx.x;
    for (int i = t; i < N_E; i += gridDim.x * blockDim.x) g_hist[i] = 0;
}

__global__ __launch_bounds__(THREADS)
void vq_main(const float* __restrict__ z, const float* __restrict__ cb,
             float* __restrict__ out, int npos) {
    __shared__ __align__(16) float sc[CHUNK * C_DIM];   // 16 KB codebook tile
    __shared__ float sred[THREADS / 32];

    const int tid = threadIdx.x;
    const int p   = blockIdx.x * THREADS + tid;   // position id
    const int b   = p / HW;
    const int hw  = p % HW;
    const float* zbase = z + ((size_t)b * C_DIM) * HW + hw;

    // this position's 64-dim vector (coalesced strided loads)
    float zreg[C_DIM];
#pragma unroll
    for (int k = 0; k < C_DIM; k++) zreg[k] = zbase[(size_t)k * HW];

    float best  = -INFINITY;
    int   bestj = 0;

    for (int c0 = 0; c0 < N_E; c0 += CHUNK) {
        __syncthreads();
        const float4* src = (const float4*)(cb + (size_t)c0 * C_DIM);
        float4*       dst = (float4*)sc;
#pragma unroll
        for (int i = 0; i < (CHUNK * C_DIM / 4) / THREADS; i++)
            dst[tid + i * THREADS] = src[tid + i * THREADS];
        __syncthreads();

        for (int j = 0; j < CHUNK; j++) {
            const float4* crow = (const float4*)(sc + j * C_DIM);
            float a0 = 0.f, a1 = 0.f, a2 = 0.f, a3 = 0.f;
#pragma unroll
            for (int k = 0; k < C_DIM / 4; k++) {
                float4 c4 = crow[k];                // broadcast LDS.128
                a0 = fmaf(zreg[4 * k + 0], c4.x, a0);
                a1 = fmaf(zreg[4 * k + 1], c4.y, a1);
                a2 = fmaf(zreg[4 * k + 2], c4.z, a2);
                a3 = fmaf(zreg[4 * k + 3], c4.w, a3);
            }
            float dot = (a0 + a1) + (a2 + a3);
            if (dot > best) { best = dot; bestj = c0 + j; }   // first-max tie-break
        }
    }

    // epilogue: z_q scatter (back to [B,C,H,W]), loss partial, index, histogram
    const float* q     = cb + (size_t)bestj * C_DIM;
    float*       obase = out + ((size_t)b * C_DIM) * HW + hw;
    float lsum = 0.f;
#pragma unroll
    for (int k = 0; k < C_DIM; k++) {
        float qk = q[k];
        obase[(size_t)k * HW] = qk;
        float d = qk - zreg[k];
        lsum = fmaf(d, d, lsum);
    }
    out[(size_t)npos * C_DIM + 2 + p] = (float)bestj;   // indices region
    atomicAdd(&g_hist[bestj], 1);                       // int atomics: deterministic

    // deterministic per-block loss partial (no float atomics)
#pragma unroll
    for (int o = 16; o; o >>= 1) lsum += __shfl_down_sync(0xffffffffu, lsum, o);
    if ((tid & 31) == 0) sred[tid >> 5] = lsum;
    __syncthreads();
    if (tid == 0) {
        float tot = 0.f;
#pragma unroll
        for (int w = 0; w < THREADS / 32; w++) tot += sred[w];
        g_partial[blockIdx.x] = tot;
    }
}

__global__ void vq_final(float* __restrict__ out, int npos, int nblocks) {
    __shared__ double sh[256];
    const int t = threadIdx.x;

    double loss = 0.0;
    for (int i = t; i < nblocks; i += 256) loss += (double)g_partial[i];

    double ent  = 0.0;
    float  invN = 1.0f / (float)npos;
    for (int i = t; i < N_E; i += 256) {
        float e = (float)g_hist[i] * invN;
        ent += (double)(e * logf(e + 1e-10f));
    }

    sh[t] = loss;
    __syncthreads();
    for (int s = 128; s; s >>= 1) { if (t < s) sh[t] += sh[t + s]; __syncthreads(); }
    double losstot = sh[0];
    __syncthreads();

    sh[t] = ent;
    __syncthreads();
    for (int s = 128; s; s >>= 1) { if (t < s) sh[t] += sh[t + s]; __syncthreads(); }

    if (t == 0) {
        out[(size_t)npos * C_DIM]     =
            (float)(1.25 * losstot / ((double)npos * (double)C_DIM));
        out[(size_t)npos * C_DIM + 1] = expf(-(float)sh[0]);
    }
}

extern "C" void kernel_launch(void* const* d_in, const int* in_sizes, int n_in,
                              void* d_out, int out_size) {
    const float* z    = (const float*)d_in[0];
    const float* cb   = (const float*)d_in[1];
    float*       out  = (float*)d_out;
    const int    npos = in_sizes[0] / C_DIM;     // 65536
    const int    nblk = npos / THREADS;          // 512

    vq_zero<<<8, 256>>>();
    vq_main<<<nblk, THREADS>>>(z, cb, out, npos);
    vq_final<<<1, 256>>>(out, npos, nblk);
}

// round 3
// speedup vs baseline: 1.0338x; 1.0338x over previous
#include <cuda_runtime.h>
#include <math.h>

#define THREADS 128
#define CHUNK   64          // codes per smem tile
#define C_DIM   64          // embedding dim
#define N_E     2048        // codebook size
#define HW      4096        // H*W

__device__ int   g_hist[N_E];
__device__ float g_partial[1024];

__device__ __forceinline__ void ffma2(unsigned long long& acc,
                                      unsigned long long a,
                                      unsigned long long b) {
    asm("fma.rn.f32x2 %0, %1, %2, %3;" : "=l"(acc) : "l"(a), "l"(b), "l"(acc));
}

__global__ void vq_zero() {
    int t = blockIdx.x * blockDim.x + threadIdx.x;
    for (int i = t; i < N_E; i += gridDim.x * blockDim.x) g_hist[i] = 0;
}

__global__ __launch_bounds__(THREADS)
void vq_main(const float* __restrict__ z, const float* __restrict__ cb,
             float* __restrict__ out, int npos) {
    __shared__ __align__(16) float sc[CHUNK * C_DIM];   // 16 KB codebook tile
    __shared__ float sred[THREADS / 32];

    const int tid = threadIdx.x;
    const int p   = blockIdx.x * THREADS + tid;   // position id
    const int b   = p / HW;
    const int hw  = p % HW;
    const float* zbase = z + ((size_t)b * C_DIM) * HW + hw;

    // this position's 64-dim vector, packed as 32 x f32x2 (lo=even dim, hi=odd dim)
    unsigned long long zp[C_DIM / 2];
#pragma unroll
    for (int k = 0; k < C_DIM / 2; k++) {
        float a0 = zbase[(size_t)(2 * k) * HW];
        float a1 = zbase[(size_t)(2 * k + 1) * HW];
        zp[k] = (unsigned long long)__float_as_uint(a0) |
                ((unsigned long long)__float_as_uint(a1) << 32);
    }

    float best  = -INFINITY;
    int   bestj = 0;

    for (int c0 = 0; c0 < N_E; c0 += CHUNK) {
        __syncthreads();
        const float4* src = (const float4*)(cb + (size_t)c0 * C_DIM);
        float4*       dst = (float4*)sc;
#pragma unroll
        for (int i = 0; i < (CHUNK * C_DIM / 4) / THREADS; i++)
            dst[tid + i * THREADS] = src[tid + i * THREADS];
        __syncthreads();

#pragma unroll 2
        for (int j = 0; j < CHUNK; j++) {
            const ulonglong2* crow = (const ulonglong2*)(sc + j * C_DIM);
            unsigned long long acc0 = 0ull, acc1 = 0ull;
#pragma unroll
            for (int k = 0; k < C_DIM / 4; k++) {
                ulonglong2 c4 = crow[k];          // broadcast LDS.128 -> 2 packed pairs
                ffma2(acc0, zp[2 * k],     c4.x);
                ffma2(acc1, zp[2 * k + 1], c4.y);
            }
            float dot = (__uint_as_float((unsigned)acc0) +
                         __uint_as_float((unsigned)(acc0 >> 32))) +
                        (__uint_as_float((unsigned)acc1) +
                         __uint_as_float((unsigned)(acc1 >> 32)));
            if (dot > best) { best = dot; bestj = c0 + j; }   // first-max tie-break
        }
    }

    // epilogue: z_q scatter (back to [B,C,H,W]), loss partial, index, histogram
    const float* q     = cb + (size_t)bestj * C_DIM;
    float*       obase = out + ((size_t)b * C_DIM) * HW + hw;
    float lsum = 0.f;
#pragma unroll
    for (int k = 0; k < C_DIM / 2; k++) {
        float q0 = q[2 * k], q1 = q[2 * k + 1];
        float z0 = __uint_as_float((unsigned)zp[k]);
        float z1 = __uint_as_float((unsigned)(zp[k] >> 32));
        obase[(size_t)(2 * k) * HW]     = q0;
        obase[(size_t)(2 * k + 1) * HW] = q1;
        float d0 = q0 - z0, d1 = q1 - z1;
        lsum = fmaf(d0, d0, lsum);
        lsum = fmaf(d1, d1, lsum);
    }
    out[(size_t)npos * C_DIM + 2 + p] = (float)bestj;   // indices region
    atomicAdd(&g_hist[bestj], 1);                       // int atomics: deterministic

    // deterministic per-block loss partial (no float atomics)
#pragma unroll
    for (int o = 16; o; o >>= 1) lsum += __shfl_down_sync(0xffffffffu, lsum, o);
    if ((tid & 31) == 0) sred[tid >> 5] = lsum;
    __syncthreads();
    if (tid == 0) {
        float tot = 0.f;
#pragma unroll
        for (int w = 0; w < THREADS / 32; w++) tot += sred[w];
        g_partial[blockIdx.x] = tot;
    }
}

__global__ void vq_final(float* __restrict__ out, int npos, int nblocks) {
    __shared__ double sh[256];
    const int t = threadIdx.x;

    double loss = 0.0;
    for (int i = t; i < nblocks; i += 256) loss += (double)g_partial[i];

    double ent  = 0.0;
    float  invN = 1.0f / (float)npos;
    for (int i = t; i < N_E; i += 256) {
        float e = (float)g_hist[i] * invN;
        ent += (double)(e * logf(e + 1e-10f));
    }

    sh[t] = loss;
    __syncthreads();
    for (int s = 128; s; s >>= 1) { if (t < s) sh[t] += sh[t + s]; __syncthreads(); }
    double losstot = sh[0];
    __syncthreads();

    sh[t] = ent;
    __syncthreads();
    for (int s = 128; s; s >>= 1) { if (t < s) sh[t] += sh[t + s]; __syncthreads(); }

    if (t == 0) {
        out[(size_t)npos * C_DIM]     =
            (float)(1.25 * losstot / ((double)npos * (double)C_DIM));
        out[(size_t)npos * C_DIM + 1] = expf(-(float)sh[0]);
    }
}

extern "C" void kernel_launch(void* const* d_in, const int* in_sizes, int n_in,
                              void* d_out, int out_size) {
    const float* z    = (const float*)d_in[0];
    const float* cb   = (const float*)d_in[1];
    float*       out  = (float*)d_out;
    const int    npos = in_sizes[0] / C_DIM;     // 65536
    const int    nblk = npos / THREADS;          // 512

    vq_zero<<<8, 256>>>();
    vq_main<<<nblk, THREADS>>>(z, cb, out, npos);
    vq_final<<<1, 256>>>(out, npos, nblk);
}

// round 5
// speedup vs baseline: 1.6167x; 1.5638x over previous
#include <cuda_runtime.h>
#include <cuda_bf16.h>
#include <math.h>
#include <stdint.h>

#define C_DIM   64
#define N_E     2048
#define HW      4096
#define NPOS    65536
#define KSEG    6
#define KTOT    (KSEG * C_DIM)     // 384
#define MT      128                // positions per CTA
#define NT      64                 // codes per chunk
#define NCHUNKS (N_E / NT)         // 32
#define NK      (KTOT / 16)        // 24 k-steps

#define ROWB    784                // smem row stride bytes: 384*2 + 16 pad
#define A_OFF   0
#define A_SZ    (MT * ROWB)        // 100352
#define B_OFF   A_SZ
#define B_SZ    (NT * ROWB)        // 50176
#define SM_DYN  (A_SZ + 2 * B_SZ)  // 200704

__device__ __align__(16) __nv_bfloat16 g_A[(size_t)NPOS * KTOT];
__device__ __align__(16) __nv_bfloat16 g_B[(size_t)N_E * KTOT];
__device__ int   g_hist[N_E];
__device__ float g_partial[512];

// ---------------- helpers ----------------
__device__ __forceinline__ uint32_t smem_u32(const void* p) {
    uint32_t a;
    asm("{ .reg .u64 t; cvta.to.shared.u64 t, %1; cvt.u32.u64 %0, t; }" : "=r"(a) : "l"(p));
    return a;
}
__device__ __forceinline__ void cp16(uint32_t dst, const void* src) {
    asm volatile("cp.async.cg.shared.global [%0], [%1], 16;" :: "r"(dst), "l"(src) : "memory");
}
#define CP_COMMIT() asm volatile("cp.async.commit_group;" ::: "memory")
#define CP_WAIT1()  asm volatile("cp.async.wait_group 1;" ::: "memory")
#define CP_WAIT0()  asm volatile("cp.async.wait_group 0;" ::: "memory")

__device__ __forceinline__ void ldmx4(uint32_t& r0, uint32_t& r1, uint32_t& r2,
                                      uint32_t& r3, uint32_t a) {
    asm volatile("ldmatrix.sync.aligned.m8n8.x4.shared.b16 {%0,%1,%2,%3}, [%4];"
                 : "=r"(r0), "=r"(r1), "=r"(r2), "=r"(r3) : "r"(a));
}
__device__ __forceinline__ void mma16816(float* c, uint32_t a0, uint32_t a1,
                                         uint32_t a2, uint32_t a3,
                                         uint32_t b0, uint32_t b1) {
    asm volatile(
        "mma.sync.aligned.m16n8k16.row.col.f32.bf16.bf16.f32 "
        "{%0,%1,%2,%3}, {%4,%5,%6,%7}, {%8,%9}, {%0,%1,%2,%3};"
        : "+f"(c[0]), "+f"(c[1]), "+f"(c[2]), "+f"(c[3])
        : "r"(a0), "r"(a1), "r"(a2), "r"(a3), "r"(b0), "r"(b1));
}

// ---------------- phase 0 ----------------
__global__ void vq_zero() {
    int t = blockIdx.x * blockDim.x + threadIdx.x;
    for (int i = t; i < N_E; i += gridDim.x * blockDim.x) g_hist[i] = 0;
}

// ---------------- bf16 triple split ----------------
__device__ __forceinline__ void split3(float v, __nv_bfloat16* o) {
    __nv_bfloat16 h = __float2bfloat16_rn(v);
    float r1 = v - __bfloat162float(h);
    __nv_bfloat16 m = __float2bfloat16_rn(r1);
    float r2 = r1 - __bfloat162float(m);
    o[0] = h; o[1] = m; o[2] = __float2bfloat16_rn(r2);
}
__constant__ int c_segA[KSEG] = {0, 0, 1, 1, 0, 2};   // h h m m h l
__constant__ int c_segB[KSEG] = {0, 1, 0, 1, 2, 0};   // h m h m l h

__global__ __launch_bounds__(256)
void vq_split_z(const float* __restrict__ z) {
    __shared__ float zt[64 * 65];
    const int t    = threadIdx.x;
    const int pos0 = blockIdx.x * 64;
    const int b    = pos0 >> 12;
    const int hw0  = pos0 & (HW - 1);
    const float* zb = z + ((size_t)b * C_DIM) * HW + hw0;

#pragma unroll
    for (int i = 0; i < 16; i++) {
        int idx = i * 256 + t;
        int d = idx >> 6, pp = idx & 63;
        zt[pp * 65 + d] = zb[(size_t)d * HW + pp];
    }
    __syncthreads();

    __nv_bfloat162* A2 = (__nv_bfloat162*)g_A;
#pragma unroll
    for (int j = 0; j < 48; j++) {
        int idx = j * 256 + t;
        int pp  = idx / 192;
        int kp  = idx - pp * 192;
        int seg = kp >> 5;
        int d0  = (2 * kp) & 63;
        __nv_bfloat16 s0[3], s1[3];
        split3(zt[pp * 65 + d0],     s0);
        split3(zt[pp * 65 + d0 + 1], s1);
        int sa = c_segA[seg];
        __nv_bfloat162 o; o.x = s0[sa]; o.y = s1[sa];
        A2[(size_t)(pos0 + pp) * 192 + kp] = o;
    }
}

__global__ __launch_bounds__(256)
void vq_split_cb(const float* __restrict__ cb) {
    int idx = blockIdx.x * 256 + threadIdx.x;
    if (idx >= N_E * 192) return;
    int code = idx / 192;
    int kp   = idx - code * 192;
    int seg  = kp >> 5;
    int d0   = (2 * kp) & 63;
    __nv_bfloat16 s0[3], s1[3];
    split3(cb[code * C_DIM + d0],     s0);
    split3(cb[code * C_DIM + d0 + 1], s1);
    int sb = c_segB[seg];
    __nv_bfloat162 o; o.x = s0[sb]; o.y = s1[sb];
    ((__nv_bfloat162*)g_B)[(size_t)code * 192 + kp] = o;
}

// ---------------- phase 2: HMMA GEMM + fused argmax ----------------
__global__ __launch_bounds__(256, 1)
void vq_mma(float* __restrict__ out, int npos) {
    extern __shared__ __align__(16) char smem[];
    const uint32_t sb   = smem_u32(smem);
    const int tid  = threadIdx.x;
    const int lane = tid & 31;
    const int w    = tid >> 5;
    const int tile0 = blockIdx.x * MT;

    // prologue: A tile (cp.async) + B chunk 0, one group
    {
        const uint4* Ag = (const uint4*)g_A + (size_t)tile0 * 48;
#pragma unroll
        for (int i = 0; i < 24; i++) {
            int idx = tid + i * 256;
            int r = idx / 48, q = idx - r * 48;
            cp16(sb + A_OFF + r * ROWB + q * 16, Ag + (size_t)r * 48 + q);
        }
        const uint4* Bg = (const uint4*)g_B;     // chunk 0
#pragma unroll
        for (int i = 0; i < 12; i++) {
            int idx = tid + i * 256;
            int r = idx / 48, q = idx - r * 48;
            cp16(sb + B_OFF + r * ROWB + q * 16, Bg + (size_t)r * 48 + q);
        }
        CP_COMMIT();
    }

    // per-lane ldmatrix base addresses
    const uint32_t aBase = sb + A_OFF +
        ((w & 3) * 32 + (lane & 15)) * ROWB + ((lane >> 4) << 3) * 2;
    const uint32_t bRel  =
        (((w >> 2) << 5) + ((lane & 16) >> 1) + (lane & 7)) * ROWB + (lane & 8) * 2;

    float best[4] = {-INFINITY, -INFINITY, -INFINITY, -INFINITY};
    int   bidx[4] = {0, 0, 0, 0};

#pragma unroll 1
    for (int nc = 0; nc < NCHUNKS; nc++) {
        if (nc + 1 < NCHUNKS) {
            const uint4* Bg = (const uint4*)g_B + (size_t)(nc + 1) * NT * 48;
            uint32_t boff = sb + B_OFF + ((nc + 1) & 1) * B_SZ;
#pragma unroll
            for (int i = 0; i < 12; i++) {
                int idx = tid + i * 256;
                int r = idx / 48, q = idx - r * 48;
                cp16(boff + r * ROWB + q * 16, Bg + (size_t)r * 48 + q);
            }
            CP_COMMIT();
            CP_WAIT1();
        } else {
            CP_WAIT0();
        }
        __syncthreads();

        const uint32_t bBase = sb + B_OFF + (nc & 1) * B_SZ + bRel;

        float acc[2][4][4];
#pragma unroll
        for (int m = 0; m < 2; m++)
#pragma unroll
            for (int n = 0; n < 4; n++)
#pragma unroll
                for (int e = 0; e < 4; e++) acc[m][n][e] = 0.f;

#pragma unroll
        for (int s = 0; s < NK; s++) {
            uint32_t a0, a1, a2, a3, a4, a5, a6, a7;
            ldmx4(a0, a1, a2, a3, aBase + s * 32);
            ldmx4(a4, a5, a6, a7, aBase + 16 * ROWB + s * 32);
            uint32_t b0, b1, b2, b3, b4, b5, b6, b7;
            ldmx4(b0, b1, b2, b3, bBase + s * 32);
            ldmx4(b4, b5, b6, b7, bBase + 16 * ROWB + s * 32);

            mma16816(acc[0][0], a0, a1, a2, a3, b0, b1);
            mma16816(acc[0][1], a0, a1, a2, a3, b2, b3);
            mma16816(acc[0][2], a0, a1, a2, a3, b4, b5);
            mma16816(acc[0][3], a0, a1, a2, a3, b6, b7);
            mma16816(acc[1][0], a4, a5, a6, a7, b0, b1);
            mma16816(acc[1][1], a4, a5, a6, a7, b2, b3);
            mma16816(acc[1][2], a4, a5, a6, a7, b4, b5);
            mma16816(acc[1][3], a4, a5, a6, a7, b6, b7);
        }

        // fused argmax over this chunk (ascending col within thread -> first-max)
        const int cbase = nc * NT + ((w >> 2) << 5) + ((lane & 3) << 1);
#pragma unroll
        for (int m = 0; m < 2; m++) {
#pragma unroll
            for (int n = 0; n < 4; n++) {
                int c0 = cbase + n * 8;
                float v0 = acc[m][n][0], v1 = acc[m][n][1];
                float v2 = acc[m][n][2], v3 = acc[m][n][3];
                int slo = m * 2, shi = m * 2 + 1;
                if (v0 > best[slo]) { best[slo] = v0; bidx[slo] = c0; }
                if (v1 > best[slo]) { best[slo] = v1; bidx[slo] = c0 + 1; }
                if (v2 > best[shi]) { best[shi] = v2; bidx[shi] = c0; }
                if (v3 > best[shi]) { best[shi] = v3; bidx[shi] = c0 + 1; }
            }
        }
        __syncthreads();   // compute done before buffer overwrite next iter
    }

    // cross-lane merge within groups of 4 (same rows, interleaved cols)
#pragma unroll
    for (int s = 0; s < 4; s++) {
        float v = best[s]; int ix = bidx[s];
#pragma unroll
        for (int d = 1; d <= 2; d <<= 1) {
            float ov = __shfl_xor_sync(0xffffffffu, v, d);
            int   oi = __shfl_xor_sync(0xffffffffu, ix, d);
            if (ov > v || (ov == v && oi < ix)) { v = ov; ix = oi; }
        }
        best[s] = v; bidx[s] = ix;
    }

    // stash per-half results (reuse A smem region; all compute is done)
    float* sbv = (float*)smem;            // [128][2]
    int*   sbi = (int*)(smem + 1024);     // [128][2]
    const int half = w >> 2;
    if ((lane & 3) == 0) {
#pragma unroll
        for (int s = 0; s < 4; s++) {
            int r = (w & 3) * 32 + (s >> 1) * 16 + (s & 1) * 8 + (lane >> 2);
            sbv[r * 2 + half] = best[s];
            sbi[r * 2 + half] = bidx[s];
        }
    }
    __syncthreads();

    if (tid < MT) {
        float v0 = sbv[tid * 2], v1 = sbv[tid * 2 + 1];
        int   i0 = sbi[tid * 2], i1 = sbi[tid * 2 + 1];
        int bj = (v1 > v0 || (v1 == v0 && i1 < i0)) ? i1 : i0;
        out[(size_t)npos * C_DIM + 2 + tile0 + tid] = (float)bj;
        atomicAdd(&g_hist[bj], 1);
    }
}

// ---------------- phase 3: z_q scatter + loss partials ----------------
__global__ __launch_bounds__(128)
void vq_epilogue(const float* __restrict__ z, const float* __restrict__ cb,
                 float* __restrict__ out, int npos) {
    __shared__ float sred[4];
    const int tid = threadIdx.x;
    const int p   = blockIdx.x * 128 + tid;
    const int b   = p >> 12;
    const int hw  = p & (HW - 1);
    const int bestj = (int)out[(size_t)npos * C_DIM + 2 + p];

    const float* q     = cb + (size_t)bestj * C_DIM;
    const float* zbase = z   + ((size_t)b * C_DIM) * HW + hw;
    float*       obase = out + ((size_t)b * C_DIM) * HW + hw;

    float lsum = 0.f;
#pragma unroll
    for (int k = 0; k < C_DIM; k++) {
        float qk = q[k];
        float zk = zbase[(size_t)k * HW];
        obase[(size_t)k * HW] = qk;
        float d = qk - zk;
        lsum = fmaf(d, d, lsum);
    }
#pragma unroll
    for (int o = 16; o; o >>= 1) lsum += __shfl_down_sync(0xffffffffu, lsum, o);
    if ((tid & 31) == 0) sred[tid >> 5] = lsum;
    __syncthreads();
    if (tid == 0)
        g_partial[blockIdx.x] = (sred[0] + sred[1]) + (sred[2] + sred[3]);
}

// ---------------- phase 4: finalize ----------------
__global__ void vq_final(float* __restrict__ out, int npos, int nblocks) {
    __shared__ double sh[256];
    const int t = threadIdx.x;

    double loss = 0.0;
    for (int i = t; i < nblocks; i += 256) loss += (double)g_partial[i];
    double ent  = 0.0;
    float  invN = 1.0f / (float)npos;
    for (int i = t; i < N_E; i += 256) {
        float e = (float)g_hist[i] * invN;
        ent += (double)(e * logf(e + 1e-10f));
    }
    sh[t] = loss; __syncthreads();
    for (int s = 128; s; s >>= 1) { if (t < s) sh[t] += sh[t + s]; __syncthreads(); }
    double losstot = sh[0]; __syncthreads();
    sh[t] = ent; __syncthreads();
    for (int s = 128; s; s >>= 1) { if (t < s) sh[t] += sh[t + s]; __syncthreads(); }
    if (t == 0) {
        out[(size_t)npos * C_DIM]     =
            (float)(1.25 * losstot / ((double)npos * (double)C_DIM));
        out[(size_t)npos * C_DIM + 1] = expf(-(float)sh[0]);
    }
}

extern "C" void kernel_launch(void* const* d_in, const int* in_sizes, int n_in,
                              void* d_out, int out_size) {
    const float* z    = (const float*)d_in[0];
    const float* cb   = (const float*)d_in[1];
    float*       out  = (float*)d_out;
    const int    npos = in_sizes[0] / C_DIM;     // 65536

    cudaFuncSetAttribute(vq_mma, cudaFuncAttributeMaxDynamicSharedMemorySize, SM_DYN);

    vq_zero<<<8, 256>>>();
    vq_split_z<<<NPOS / 64, 256>>>(z);
    vq_split_cb<<<(N_E * 192 + 255) / 256, 256>>>(cb);
    vq_mma<<<NPOS / MT, 256, SM_DYN>>>(out, npos);
    vq_epilogue<<<NPOS / 128, 128>>>(z, cb, out, npos);
    vq_final<<<1, 256>>>(out, npos, NPOS / 128);
}